// round 1
// baseline (speedup 1.0000x reference)
#include <cuda_runtime.h>

#define S_LEN 262144
#define NDIM 128
#define TILE_ROWS 128
#define NBLOCKS (S_LEN / TILE_ROWS)   // 2048
#define LDI 132                        // padded smem row stride (floats)

// ---------------- device scratch (no allocations allowed) ----------------
__device__ float g_W[NDIM * NDIM];        // M = W_K^T @ W_Q
__device__ float g_partials[NBLOCKS];     // per-block loss partial sums

// ---------------- f32x2 helpers ----------------
__device__ __forceinline__ unsigned long long ffma2(unsigned long long a,
                                                    unsigned long long b,
                                                    unsigned long long c) {
    unsigned long long d;
    asm("fma.rn.f32x2 %0, %1, %2, %3;" : "=l"(d) : "l"(a), "l"(b), "l"(c));
    return d;
}
__device__ __forceinline__ unsigned long long pack2(float x) {
    unsigned long long r;
    asm("mov.b64 %0, {%1, %1};" : "=l"(r) : "r"(__float_as_uint(x)));
    return r;
}
__device__ __forceinline__ float lo2(unsigned long long v) {
    return __uint_as_float((unsigned)(v & 0xffffffffull));
}
__device__ __forceinline__ float hi2(unsigned long long v) {
    return __uint_as_float((unsigned)(v >> 32));
}

__device__ __forceinline__ float softplusf(float x) {
    if (x > 20.0f) return x;               // exp(x) would dominate; softplus(x)≈x, err < 2e-9
    return log1pf(__expf(x));
}

// ---------------- kernel A: M = W_K^T @ W_Q ----------------
// M[i][t] = sum_j W_K[j][i] * W_Q[j][t]
__global__ void compute_W_kernel(const float* __restrict__ WQ,
                                 const float* __restrict__ WK) {
    __shared__ float colK[NDIM];
    const int i = blockIdx.x;    // output row of M
    const int t = threadIdx.x;   // output col of M
    colK[t] = WK[t * NDIM + i];  // W_K[j=t][i]
    __syncthreads();
    float acc = 0.0f;
#pragma unroll 8
    for (int j = 0; j < NDIM; ++j)
        acc = fmaf(colK[j], WQ[j * NDIM + t], acc);
    g_W[i * NDIM + t] = acc;
}

// ---------------- kernel B: fused GEMM + softplus + rowsum + loss partial ----------------
extern __shared__ float smem[];

__global__ __launch_bounds__(256, 1)
void fused_main_kernel(const float* __restrict__ In) {
    float* sW      = smem;                         // 128*128
    float* sIn     = sW + NDIM * NDIM;             // 129 rows * LDI
    float* sRowsum = sIn + 129 * LDI;              // 128
    float* sRed    = sRowsum + TILE_ROWS;          // 256

    const int tid  = threadIdx.x;
    const int base = blockIdx.x * TILE_ROWS;

    // stage M (64KB) — coalesced float4
    {
        const float4* src = (const float4*)g_W;
        float4*       dst = (float4*)sW;
#pragma unroll 4
        for (int k = tid; k < NDIM * NDIM / 4; k += 256) dst[k] = src[k];
    }
    // stage Input rows [base, base+128] (129 rows; last row zero-padded at end of tensor)
    {
        const float4* src = (const float4*)In;
        for (int k = tid; k < 129 * (NDIM / 4); k += 256) {
            const int row = k >> 5;          // /32
            const int c4  = k & 31;          // %32
            const int grow = base + row;
            float4 v = make_float4(0.f, 0.f, 0.f, 0.f);
            if (grow < S_LEN) v = src[grow * (NDIM / 4) + c4];
            *((float4*)(sIn + row * LDI + c4 * 4)) = v;
        }
    }
    __syncthreads();

    // per-row sums of Input (rows 0..127 of the tile)
    if (tid < TILE_ROWS) {
        const float* r = sIn + tid * LDI;
        float s = 0.f;
#pragma unroll 8
        for (int i = 0; i < NDIM; ++i) s += r[i];
        sRowsum[tid] = s;
    }
    __syncthreads();

    // thread tile: 8 rows (strided by 16) x 8 cols (4 f32x2 pairs)
    const int cg = tid & 15;    // column group 0..15
    const int rg = tid >> 4;    // row group    0..15
    const int c0 = cg * 8;

    unsigned long long acc[8][4];
#pragma unroll
    for (int k = 0; k < 8; ++k)
#pragma unroll
        for (int c = 0; c < 4; ++c) acc[k][c] = 0ull;

#pragma unroll 2
    for (int i = 0; i < NDIM; ++i) {
        const ulonglong2* wrow = (const ulonglong2*)(sW + i * NDIM + c0);
        const ulonglong2 w01 = wrow[0];   // cols c0..c0+3 (two f32x2)
        const ulonglong2 w23 = wrow[1];   // cols c0+4..c0+7
#pragma unroll
        for (int k = 0; k < 8; ++k) {
            const float a = sIn[(rg + 16 * k) * LDI + i];
            const unsigned long long a2 = pack2(a);
            acc[k][0] = ffma2(a2, w01.x, acc[k][0]);
            acc[k][1] = ffma2(a2, w01.y, acc[k][1]);
            acc[k][2] = ffma2(a2, w23.x, acc[k][2]);
            acc[k][3] = ffma2(a2, w23.y, acc[k][3]);
        }
    }

    // epilogue: softplus * rowsum - Input[s+1], accumulate squared diff
    float lsum = 0.0f;
#pragma unroll
    for (int k = 0; k < 8; ++k) {
        const int r = rg + 16 * k;
        const int s = base + r;
        if (s < S_LEN - 1) {
            const float rs = sRowsum[r];
            const float* nxt = sIn + (r + 1) * LDI + c0;   // Input[s+1, c0..c0+7]
#pragma unroll
            for (int c = 0; c < 4; ++c) {
                const float x0 = lo2(acc[k][c]);
                const float x1 = hi2(acc[k][c]);
                const float d0 = softplusf(x0) * rs - nxt[2 * c];
                const float d1 = softplusf(x1) * rs - nxt[2 * c + 1];
                lsum = fmaf(d0, d0, lsum);
                lsum = fmaf(d1, d1, lsum);
            }
        }
    }

    // deterministic in-block tree reduction
    sRed[tid] = lsum;
    __syncthreads();
#pragma unroll
    for (int off = 128; off > 0; off >>= 1) {
        if (tid < off) sRed[tid] += sRed[tid + off];
        __syncthreads();
    }
    if (tid == 0) g_partials[blockIdx.x] = sRed[0];
}

// ---------------- kernel C: final deterministic reduce + l1 ----------------
__global__ void finalize_kernel(float* __restrict__ out) {
    __shared__ double red[256];
    const int tid = threadIdx.x;

    // loss = sum(partials) / ((S-1)*N)
    double s = 0.0;
    for (int k = tid; k < NBLOCKS; k += 256) s += (double)g_partials[k];
    red[tid] = s;
    __syncthreads();
    for (int off = 128; off > 0; off >>= 1) {
        if (tid < off) red[tid] += red[tid + off];
        __syncthreads();
    }
    if (tid == 0)
        out[0] = (float)(red[0] / ((double)(S_LEN - 1) * (double)NDIM));
    __syncthreads();

    // l1 = sum(sigmoid(M))  (sigmoid > 0, so |.| is a no-op)
    double l1 = 0.0;
    for (int k = tid; k < NDIM * NDIM; k += 256) {
        const float w = g_W[k];
        l1 += (double)(1.0f / (1.0f + __expf(-w)));
    }
    red[tid] = l1;
    __syncthreads();
    for (int off = 128; off > 0; off >>= 1) {
        if (tid < off) red[tid] += red[tid + off];
        __syncthreads();
    }
    if (tid == 0) out[1] = (float)red[0];
}

// ---------------- launch ----------------
extern "C" void kernel_launch(void* const* d_in, const int* in_sizes, int n_in,
                              void* d_out, int out_size) {
    const float* In = (const float*)d_in[0];
    const float* WQ = (const float*)d_in[1];
    const float* WK = (const float*)d_in[2];
    float* out = (float*)d_out;

    compute_W_kernel<<<NDIM, NDIM>>>(WQ, WK);

    const size_t smem_bytes =
        (size_t)(NDIM * NDIM + 129 * LDI + TILE_ROWS + 256) * sizeof(float);
    cudaFuncSetAttribute(fused_main_kernel,
                         cudaFuncAttributeMaxDynamicSharedMemorySize,
                         (int)smem_bytes);
    fused_main_kernel<<<NBLOCKS, 256, smem_bytes>>>(In);

    finalize_kernel<<<1, 256>>>(out);
}

// round 3
// speedup vs baseline: 2.6501x; 2.6501x over previous
#include <cuda_runtime.h>
#include <cuda_bf16.h>
#include <cstdint>

#define S_LEN  262144
#define NDIM   128
#define TILE   128
#define NTILES (S_LEN / TILE)   // 2048
#define GRID   148

#define LDA 132                  // A smem row stride (fp32 elems)  -> 528 B
#define LDB 136                  // B smem row stride (bf16 elems)  -> 272 B

// ---------------- device scratch ----------------
__device__ float g_W[NDIM * NDIM];                           // M (fp32, for l1)
__device__ __align__(16) __nv_bfloat16 g_B[NDIM * LDB];      // B[t][i] = bf16(M[i][t]), padded
__device__ float g_partials[GRID];

// smem byte offsets (dynamic smem, 16B aligned)
#define A0_OFF   0
#define A1_OFF   67584                    // 128*528
#define B_OFF    135168                   // + 128*528
#define NEXT_OFF 169984                   // + 128*272 = 34816
#define RED_OFF  171008                   // + 2*512
#define SMEM_BYTES 172032                 // + 1024

// ---------------- small helpers ----------------
__device__ __forceinline__ uint32_t smem_u32(const void* p) {
    uint32_t a;
    asm("{ .reg .u64 t; cvta.to.shared.u64 t, %1; cvt.u32.u64 %0, t; }" : "=r"(a) : "l"(p));
    return a;
}
__device__ __forceinline__ float2 lds64(uint32_t a) {
    float2 v;
    asm volatile("ld.shared.v2.f32 {%0,%1}, [%2];" : "=f"(v.x), "=f"(v.y) : "r"(a));
    return v;
}
__device__ __forceinline__ uint32_t lds32(uint32_t a) {
    uint32_t v;
    asm volatile("ld.shared.b32 %0, [%1];" : "=r"(v) : "r"(a));
    return v;
}
// pack bf16x2: high half = bf16(xh), low half = bf16(xl)
__device__ __forceinline__ uint32_t bf2(float xh, float xl) {
    uint32_t r;
    asm("cvt.rn.bf16x2.f32 %0, %1, %2;" : "=r"(r) : "f"(xh), "f"(xl));
    return r;
}
__device__ __forceinline__ float lo_f(uint32_t p) { return __uint_as_float(p << 16); }
__device__ __forceinline__ float hi_f(uint32_t p) { return __uint_as_float(p & 0xffff0000u); }

__device__ __forceinline__ void cpa16(uint32_t dst, const void* src) {
    asm volatile("cp.async.cg.shared.global [%0], [%1], 16;" :: "r"(dst), "l"(src));
}
__device__ __forceinline__ void cpa_commit() {
    asm volatile("cp.async.commit_group;" ::: "memory");
}
__device__ __forceinline__ void cpa_wait0() {
    asm volatile("cp.async.wait_group 0;" ::: "memory");
}

__device__ __forceinline__ void mma_bf16(float* d, const uint32_t* a, uint32_t b0, uint32_t b1) {
    asm volatile(
        "mma.sync.aligned.m16n8k16.row.col.f32.bf16.bf16.f32 "
        "{%0,%1,%2,%3}, {%4,%5,%6,%7}, {%8,%9}, {%0,%1,%2,%3};"
        : "+f"(d[0]), "+f"(d[1]), "+f"(d[2]), "+f"(d[3])
        : "r"(a[0]), "r"(a[1]), "r"(a[2]), "r"(a[3]), "r"(b0), "r"(b1));
}

__device__ __forceinline__ float softplusf(float x) {
    if (x > 15.0f) return x;
    return __logf(1.0f + __expf(x));
}

// ---------------- kernel A: M = W_K^T @ W_Q ; emit fp32 M + bf16 B^T (padded) ----------------
extern __shared__ float wsmem[];
__global__ void __launch_bounds__(256, 1)
compute_W_kernel(const float* __restrict__ WQ, const float* __restrict__ WK) {
    float* sWQ  = wsmem;                 // 128x128
    float* sWK8 = wsmem + NDIM * NDIM;   // 128x8
    const int tid = threadIdx.x;
    const int i0  = blockIdx.x * 8;

    {
        const float4* src = (const float4*)WQ;
        float4* dst = (float4*)sWQ;
#pragma unroll
        for (int k = tid; k < NDIM * NDIM / 4; k += 256) dst[k] = src[k];
    }
    for (int k = tid; k < NDIM * 8; k += 256) {
        const int j = k >> 3, u = k & 7;
        sWK8[k] = WK[j * NDIM + i0 + u];
    }
    __syncthreads();

    const int t  = tid & 127;
    const int ib = (tid >> 7) * 4;
    float acc[4] = {0.f, 0.f, 0.f, 0.f};
#pragma unroll 4
    for (int j = 0; j < NDIM; ++j) {
        const float wq = sWQ[j * NDIM + t];
#pragma unroll
        for (int u = 0; u < 4; ++u) acc[u] = fmaf(sWK8[j * 8 + ib + u], wq, acc[u]);
    }
#pragma unroll
    for (int u = 0; u < 4; ++u) {
        const int i = i0 + ib + u;                 // M row (k index)
        g_W[i * NDIM + t] = acc[u];
        g_B[t * LDB + i] = __float2bfloat16(acc[u]);  // B[t][i] = M[i][t]
    }
}

// ---------------- fused persistent kernel ----------------
extern __shared__ char dsm[];

__device__ __forceinline__ void prefetch_tile(const float* __restrict__ In, int tile,
                                              uint32_t aBuf, uint32_t nextAddr, int tid) {
    const char* src = (const char*)(In + (size_t)tile * TILE * NDIM);
#pragma unroll
    for (int j = 0; j < 16; ++j) {
        const int idx = tid + 256 * j;       // 4096 chunks of 16B
        const int row = idx >> 5;
        const int c   = idx & 31;
        cpa16(aBuf + row * 528 + c * 16, src + row * 512 + c * 16);
    }
    if (tid < 32) {
        size_t nr = (size_t)tile * TILE + TILE;     // boundary row
        if (nr >= S_LEN) nr = 0;                     // clamp; value unused
        cpa16(nextAddr + tid * 16, (const char*)(In + nr * NDIM) + tid * 16);
    }
    cpa_commit();
}

__device__ __forceinline__ float compute_tile(uint32_t aBuf, uint32_t bBase, uint32_t nextAddr,
                                              int tile, int tid) {
    const int lane = tid & 31;
    const int w    = tid >> 5;
    const int m0   = (w & 3) * 32;     // warp row base
    const int n0   = (w >> 2) * 64;    // warp col base
    const int g    = lane >> 2;
    const int q    = lane & 3;

    float dacc[2][8][4];
#pragma unroll
    for (int mf = 0; mf < 2; ++mf)
#pragma unroll
        for (int nf = 0; nf < 8; ++nf)
#pragma unroll
            for (int j = 0; j < 4; ++j) dacc[mf][nf][j] = 0.f;

    float rs[4] = {0.f, 0.f, 0.f, 0.f};

#pragma unroll 4
    for (int ks = 0; ks < 8; ++ks) {
        const int k0 = ks * 16;
        uint32_t ahi[2][4], alo[2][4];
#pragma unroll
        for (int mf = 0; mf < 2; ++mf) {
            const uint32_t base = aBuf + (uint32_t)(m0 + 16 * mf + g) * 528 + k0 * 4 + q * 8;
            const float2 v00 = lds64(base);                // row R,   k 2q,2q+1
            const float2 v01 = lds64(base + 32);           // row R,   k +8
            const float2 v10 = lds64(base + 8 * 528);      // row R+8
            const float2 v11 = lds64(base + 8 * 528 + 32);
            rs[2 * mf]     += (v00.x + v00.y) + (v01.x + v01.y);
            rs[2 * mf + 1] += (v10.x + v10.y) + (v11.x + v11.y);
            ahi[mf][0] = bf2(v00.y, v00.x);
            ahi[mf][1] = bf2(v10.y, v10.x);
            ahi[mf][2] = bf2(v01.y, v01.x);
            ahi[mf][3] = bf2(v11.y, v11.x);
            alo[mf][0] = bf2(v00.y - hi_f(ahi[mf][0]), v00.x - lo_f(ahi[mf][0]));
            alo[mf][1] = bf2(v10.y - hi_f(ahi[mf][1]), v10.x - lo_f(ahi[mf][1]));
            alo[mf][2] = bf2(v01.y - hi_f(ahi[mf][2]), v01.x - lo_f(ahi[mf][2]));
            alo[mf][3] = bf2(v11.y - hi_f(ahi[mf][3]), v11.x - lo_f(ahi[mf][3]));
        }
#pragma unroll
        for (int nf = 0; nf < 8; ++nf) {
            const uint32_t baddr = bBase + (uint32_t)(n0 + 8 * nf + g) * 272 + k0 * 2 + q * 4;
            const uint32_t b0 = lds32(baddr);
            const uint32_t b1 = lds32(baddr + 16);
#pragma unroll
            for (int mf = 0; mf < 2; ++mf) {
                mma_bf16(dacc[mf][nf], ahi[mf], b0, b1);
                mma_bf16(dacc[mf][nf], alo[mf], b0, b1);
            }
        }
    }

    // quad-reduce rowsums (lanes in a quad together cover all 128 cols of each row)
#pragma unroll
    for (int j = 0; j < 4; ++j) {
        rs[j] += __shfl_xor_sync(0xffffffffu, rs[j], 1);
        rs[j] += __shfl_xor_sync(0xffffffffu, rs[j], 2);
    }

    // epilogue: softplus * rowsum - Input[s+1], squared
    const size_t base = (size_t)tile * TILE;
    float loss = 0.f;
#pragma unroll
    for (int mf = 0; mf < 2; ++mf) {
        const int rowA = m0 + 16 * mf + g;       // <= 119
        const int rowB = rowA + 8;               // <= 127
        const float rsA = rs[2 * mf];
        const float rsB = rs[2 * mf + 1];
        const bool vB = (base + rowB) < (size_t)(S_LEN - 1);  // rowA always valid
#pragma unroll
        for (int nf = 0; nf < 8; ++nf) {
            const int col = n0 + 8 * nf + 2 * q;
            const float2 nxa = lds64(aBuf + (uint32_t)(rowA + 1) * 528 + col * 4);
            const float2 nxb = (rowB + 1 < TILE)
                                   ? lds64(aBuf + (uint32_t)(rowB + 1) * 528 + col * 4)
                                   : lds64(nextAddr + col * 4);
            const float* d = dacc[mf][nf];
            float t0 = fmaf(softplusf(d[0]), rsA, -nxa.x);
            float t1 = fmaf(softplusf(d[1]), rsA, -nxa.y);
            loss = fmaf(t0, t0, loss);
            loss = fmaf(t1, t1, loss);
            if (vB) {
                float t2 = fmaf(softplusf(d[2]), rsB, -nxb.x);
                float t3 = fmaf(softplusf(d[3]), rsB, -nxb.y);
                loss = fmaf(t2, t2, loss);
                loss = fmaf(t3, t3, loss);
            }
        }
    }
    return loss;
}

__global__ void __launch_bounds__(256, 1)
fused_kernel(const float* __restrict__ In) {
    const uint32_t sb = smem_u32(dsm);
    const int tid = threadIdx.x;

    // stage B (bf16, padded) into smem
    {
        const float4* src = (const float4*)g_B;
        float4* dst = (float4*)(dsm + B_OFF);
#pragma unroll
        for (int k = tid; k < (NDIM * LDB * 2) / 16; k += 256) dst[k] = src[k];
    }

    const int bx = blockIdx.x;
    const int nt = (NTILES - bx + GRID - 1) / GRID;

    prefetch_tile(In, bx, sb + A0_OFF, sb + NEXT_OFF, tid);
    __syncthreads();   // B staged before compute

    float loss = 0.f;
    for (int i = 0; i < nt; ++i) {
        const uint32_t aBuf = sb + ((i & 1) ? A1_OFF : A0_OFF);
        const uint32_t nxt  = sb + NEXT_OFF + (i & 1) * 512;
        cpa_wait0();
        __syncthreads();
        if (i + 1 < nt) {
            const uint32_t aN = sb + (((i + 1) & 1) ? A1_OFF : A0_OFF);
            prefetch_tile(In, bx + (i + 1) * GRID, aN, sb + NEXT_OFF + ((i + 1) & 1) * 512, tid);
        }
        loss += compute_tile(aBuf, sb + B_OFF, nxt, bx + i * GRID, tid);
        __syncthreads();   // all warps done reading aBuf before it is refilled (two iters later)
    }

    // deterministic CTA reduction
    float* sRed = (float*)(dsm + RED_OFF);
    sRed[tid] = loss;
    __syncthreads();
#pragma unroll
    for (int o = 128; o; o >>= 1) {
        if (tid < o) sRed[tid] += sRed[tid + o];
        __syncthreads();
    }
    if (tid == 0) g_partials[bx] = sRed[0];
}

// ---------------- finalize: deterministic reduce + l1 ----------------
__global__ void finalize_kernel(float* __restrict__ out) {
    __shared__ double red[256];
    const int tid = threadIdx.x;

    double ssum = 0.0;
    for (int k = tid; k < GRID; k += 256) ssum += (double)g_partials[k];
    red[tid] = ssum;
    __syncthreads();
    for (int o = 128; o; o >>= 1) {
        if (tid < o) red[tid] += red[tid + o];
        __syncthreads();
    }
    if (tid == 0)
        out[0] = (float)(red[0] / ((double)(S_LEN - 1) * (double)NDIM));
    __syncthreads();

    double l1 = 0.0;
    for (int k = tid; k < NDIM * NDIM; k += 256) {
        const float w = g_W[k];
        l1 += (double)(1.0f / (1.0f + __expf(-w)));
    }
    red[tid] = l1;
    __syncthreads();
    for (int o = 128; o; o >>= 1) {
        if (tid < o) red[tid] += red[tid + o];
        __syncthreads();
    }
    if (tid == 0) out[1] = (float)red[0];
}

// ---------------- launch ----------------
extern "C" void kernel_launch(void* const* d_in, const int* in_sizes, int n_in,
                              void* d_out, int out_size) {
    const float* In = (const float*)d_in[0];
    const float* WQ = (const float*)d_in[1];
    const float* WK = (const float*)d_in[2];
    float* out = (float*)d_out;

    const int wq_smem = (NDIM * NDIM + NDIM * 8) * sizeof(float);
    cudaFuncSetAttribute(compute_W_kernel,
                         cudaFuncAttributeMaxDynamicSharedMemorySize, wq_smem);
    compute_W_kernel<<<16, 256, wq_smem>>>(WQ, WK);

    cudaFuncSetAttribute(fused_kernel,
                         cudaFuncAttributeMaxDynamicSharedMemorySize, SMEM_BYTES);
    fused_kernel<<<GRID, 256, SMEM_BYTES>>>(In);

    finalize_kernel<<<1, 256>>>(out);
}